// round 15
// baseline (speedup 1.0000x reference)
#include <cuda_runtime.h>

// LRF_11330123727115
// Inputs : d_in[0] = neighbor (B=64, G=2048, S=64, C=3) float32 (center unused)
// Output : d_out = [ rot_neighbor (B,G,S,3) | lrfs (B,G,3,3) ] float32
//
// R15: THREE-KERNEL SPLIT — each phase at its natural operating point.
//   A1 lrf_cov   (grid 16384, 1 warp/group, low regs, full occ):
//                covariance butterfly (bit-identical FP order to R14),
//                writes 6 floats/group to scratch. Pure 100MB stream.
//   A2 lrf_solve (grid 512, one LAPACK-faithful solve per lane):
//                reads cov scratch, writes z/x eigvecs. Compute-only.
//   B  lrf_rotate(grid 16384, 1 warp/group): ballot-disambiguate + rotate +
//                coalesced stores (unchanged from R14: 35.5us, DRAM 57%).
// Eigenvector signs match jnp.linalg.eigh (ssytd2+ssteqr+sormtr fp32
// emulation) — required for the n_pos==32 disambiguation ties (~9.9%/axis).

constexpr int NG = 64 * 2048;   // 131072 groups
constexpr long long ROT_ELEMS = (long long)NG * 64 * 3;
constexpr int GPW = 32;         // groups per warp in lrf_solve

__device__ float g_cov [NG * 6];   // per-group packed lower cov
__device__ float g_vecs[NG * 6];   // per-group z(3), x(3) eigenvectors

// ---------------- LAPACK helper emulations (fp32, IEEE ops) ----------------

__device__ __forceinline__ float f_slapy2(float x, float y) {
    float ax = fabsf(x), ay = fabsf(y);
    float w = fmaxf(ax, ay), z = fminf(ax, ay);
    if (z == 0.f) return w;
    float q = __fdiv_rn(z, w);
    return w * __fsqrt_rn(1.f + q * q);
}

// LAPACK >= 3.10 slartg: r = sign(f)*sqrt(f^2+g^2), c = |f|/|r| >= 0, s = g/r
__device__ __forceinline__ void f_slartg(float f, float g, float& c, float& s, float& r) {
    if (g == 0.f)      { c = 1.f; s = 0.f; r = f; }
    else if (f == 0.f) { c = 0.f; s = copysignf(1.f, g); r = fabsf(g); }
    else {
        float d = __fsqrt_rn(f * f + g * g);
        c = __fdiv_rn(fabsf(f), d);
        r = copysignf(d, f);
        s = __fdiv_rn(g, r);
    }
}

__device__ __forceinline__ void f_slaev2(float a, float b, float c,
                                         float& rt1, float& rt2,
                                         float& cs1, float& sn1) {
    float sm = a + c, df = a - c;
    float adf = fabsf(df), tb = b + b, ab = fabsf(tb);
    float acmx, acmn;
    if (fabsf(a) > fabsf(c)) { acmx = a; acmn = c; } else { acmx = c; acmn = a; }
    float rt;
    if (adf > ab)      { float q = __fdiv_rn(ab, adf); rt = adf * __fsqrt_rn(1.f + q * q); }
    else if (adf < ab) { float q = __fdiv_rn(adf, ab); rt = ab * __fsqrt_rn(1.f + q * q); }
    else               rt = ab * __fsqrt_rn(2.f);
    int sgn1;
    if (sm < 0.f) {
        rt1 = 0.5f * (sm - rt); sgn1 = -1;
        rt2 = __fdiv_rn(acmx, rt1) * acmn - __fdiv_rn(b, rt1) * b;
    } else if (sm > 0.f) {
        rt1 = 0.5f * (sm + rt); sgn1 = 1;
        rt2 = __fdiv_rn(acmx, rt1) * acmn - __fdiv_rn(b, rt1) * b;
    } else {
        rt1 = 0.5f * rt; rt2 = -0.5f * rt; sgn1 = 1;
    }
    int sgn2; float cs;
    if (df >= 0.f) { cs = df + rt; sgn2 = 1; }
    else           { cs = df - rt; sgn2 = -1; }
    float acs = fabsf(cs);
    if (acs > ab) {
        float ct = __fdiv_rn(-tb, cs);
        sn1 = __fdiv_rn(1.f, __fsqrt_rn(1.f + ct * ct));
        cs1 = ct * sn1;
    } else if (ab == 0.f) {
        cs1 = 1.f; sn1 = 0.f;
    } else {
        float tn = __fdiv_rn(-cs, tb);
        cs1 = __fdiv_rn(1.f, __fsqrt_rn(1.f + tn * tn));
        sn1 = tn * cs1;
    }
    if (sgn1 == sgn2) { float tn = cs1; cs1 = -sn1; sn1 = tn; }
}

// ssyevd(n=3, uplo='L') emulation: ssytd2 -> ssteqr('I') -> sort -> sormtr.
// Fully register-resident. FP op sequence identical to R5..R14.
__device__ void eigh3_lapack(float a11, float a21, float a31,
                             float a22, float a32, float a33,
                             float& zvx, float& zvy, float& zvz,
                             float& xvx, float& xvy, float& xvz) {
    // ---- ssytd2 lower: one reflector annihilating a31 ----
    float d0, d1, d2, e0, e1, tau1, v3;
    {
        float xnorm = fabsf(a31);
        if (xnorm == 0.f) { tau1 = 0.f; v3 = 0.f; e0 = a21; }
        else {
            float beta = -copysignf(f_slapy2(a21, xnorm), a21);
            tau1 = __fdiv_rn(beta - a21, beta);
            v3 = a31 * __fdiv_rn(1.f, a21 - beta);
            e0 = beta;
        }
        if (tau1 != 0.f) {
            float x1 = tau1 * (a22 + a32 * v3);   // x = tau*A22*v, v=[1,v3]
            float x2 = tau1 * (a32 + a33 * v3);
            float al = -0.5f * tau1 * (x1 + x2 * v3);
            float w1 = x1 + al;
            float w2 = x2 + al * v3;
            a22 = a22 - w1 - w1;                  // A -= v w^T + w v^T
            a32 = a32 - v3 * w1 - w2;
            a33 = a33 - v3 * w2 - v3 * w2;
        }
        d0 = a11; d1 = a22; d2 = a33; e1 = a32;
    }

    // Z kept as 9 registers, z<row><col>
    float z00 = 1.f, z01 = 0.f, z02 = 0.f;
    float z10 = 0.f, z11 = 1.f, z12 = 0.f;
    float z20 = 0.f, z21 = 0.f, z22 = 1.f;

    auto dget = [&](int i) -> float { return i == 0 ? d0 : (i == 1 ? d1 : d2); };
    auto dset = [&](int i, float v) { if (i == 0) d0 = v; else if (i == 1) d1 = v; else d2 = v; };
    auto eget = [&](int i) -> float { return i == 0 ? e0 : e1; };
    auto eset = [&](int i, float v) { if (i == 0) e0 = v; else e1 = v; };
    auto zrot = [&](int lo, float cc, float ss) {
        float t;
        if (lo == 0) {
            t = z01; z01 = cc * t - ss * z00; z00 = ss * t + cc * z00;
            t = z11; z11 = cc * t - ss * z10; z10 = ss * t + cc * z10;
            t = z21; z21 = cc * t - ss * z20; z20 = ss * t + cc * z20;
        } else {
            t = z02; z02 = cc * t - ss * z01; z01 = ss * t + cc * z01;
            t = z12; z12 = cc * t - ss * z11; z11 = ss * t + cc * z11;
            t = z22; z22 = cc * t - ss * z21; z21 = ss * t + cc * z21;
        }
    };
    auto zswap = [&](int a, int b) {   // swap columns a<b
        float t;
        if (a == 0 && b == 1) {
            t = z00; z00 = z01; z01 = t;
            t = z10; z10 = z11; z11 = t;
            t = z20; z20 = z21; z21 = t;
        } else if (a == 0 && b == 2) {
            t = z00; z00 = z02; z02 = t;
            t = z10; z10 = z12; z12 = t;
            t = z20; z20 = z22; z22 = t;
        } else {
            t = z01; z01 = z02; z02 = t;
            t = z11; z11 = z12; z12 = t;
            t = z21; z21 = z22; z22 = t;
        }
    };

    // ---- ssteqr('I', n=3) ----
    const float eps    = 5.9604645e-08f;   // slamch('E') for IEEE single
    const float eps2   = eps * eps;
    const float safmin = 1.1754944e-38f;
    const int   nmaxit = 90;               // 3 * 30
    int jtot = 0, l1 = 1;
    float wc0 = 0.f, wc1 = 0.f, ws0 = 0.f, ws1 = 0.f;
    auto wcget = [&](int i) -> float { return i == 0 ? wc0 : wc1; };
    auto wsget = [&](int i) -> float { return i == 0 ? ws0 : ws1; };
    auto wcset = [&](int i, float v) { if (i == 0) wc0 = v; else wc1 = v; };
    auto wsset = [&](int i, float v) { if (i == 0) ws0 = v; else ws1 = v; };

    for (;;) {                                       // label 10
        if (l1 > 3) break;
        if (l1 > 1) eset(l1 - 2, 0.f);
        int m = 3;
        if (l1 <= 2) {
            for (int mm = l1; mm <= 2; mm++) {
                float tst = fabsf(eget(mm - 1));
                if (tst == 0.f) { m = mm; break; }
                if (tst <= (__fsqrt_rn(fabsf(dget(mm - 1))) *
                            __fsqrt_rn(fabsf(dget(mm)))) * eps) {
                    eset(mm - 1, 0.f); m = mm; break;
                }
            }
        }
        int l = l1, lsv = l, lend = m, lendsv = lend;
        l1 = m + 1;
        if (lend == l) continue;
        float anorm = 0.f;
        for (int i = l; i <= lend; i++)     anorm = fmaxf(anorm, fabsf(dget(i - 1)));
        for (int i = l; i <= lend - 1; i++) anorm = fmaxf(anorm, fabsf(eget(i - 1)));
        if (anorm == 0.f) continue;
        if (fabsf(dget(lend - 1)) < fabsf(dget(l - 1))) { lend = lsv; l = lendsv; }

        if (lend > l) {
            // ================= QL iteration =================
            for (;;) {                                // label 40
                int m2 = lend;
                if (l != lend) {
                    for (int mm = l; mm <= lend - 1; mm++) {
                        float ev = eget(mm - 1);
                        float tst = ev * ev;
                        if (tst <= (eps2 * fabsf(dget(mm - 1))) * fabsf(dget(mm)) + safmin) {
                            m2 = mm; break;
                        }
                    }
                }
                if (m2 < lend) eset(m2 - 1, 0.f);
                float p = dget(l - 1);
                if (m2 == l) {                        // eigenvalue found
                    dset(l - 1, p); l++;
                    if (l <= lend) continue;
                    break;
                }
                if (m2 == l + 1) {                    // 2x2 deflation
                    float rt1, rt2, c2, s2;
                    f_slaev2(dget(l - 1), eget(l - 1), dget(l), rt1, rt2, c2, s2);
                    zrot(l - 1, c2, s2);
                    dset(l - 1, rt1); dset(l, rt2); eset(l - 1, 0.f);
                    l += 2;
                    if (l <= lend) continue;
                    break;
                }
                if (jtot == nmaxit) break;
                jtot++;
                float g = __fdiv_rn(dget(l) - p, 2.f * eget(l - 1));
                float r = f_slapy2(g, 1.f);
                g = dget(m2 - 1) - p + __fdiv_rn(eget(l - 1), g + copysignf(r, g));
                float sv = 1.f, cv = 1.f;
                p = 0.f;
                for (int i = m2 - 1; i >= l; i--) {
                    float f = sv * eget(i - 1);
                    float b = cv * eget(i - 1);
                    f_slartg(g, f, cv, sv, r);
                    if (i != m2 - 1) eset(i, r);
                    g = dget(i) - p;
                    r = (dget(i - 1) - g) * sv + 2.f * cv * b;
                    p = sv * r;
                    dset(i, g + p);
                    g = cv * r - b;
                    wcset(i - 1, cv); wsset(i - 1, -sv);
                }
                int mm = m2 - l + 1;                  // slasr 'R','V','B'
                for (int j = mm - 1; j >= 1; j--) {
                    float cc = wcget(l + j - 2), ssv = wsget(l + j - 2);
                    zrot(l + j - 2, cc, ssv);
                }
                dset(l - 1, dget(l - 1) - p);
                eset(l - 1, g);
            }
        } else {
            // ================= QR iteration =================
            for (;;) {                                // label 90
                int m2 = lend;
                if (l != lend) {
                    for (int mm = l; mm >= lend + 1; mm--) {
                        float ev = eget(mm - 2);
                        float tst = ev * ev;
                        if (tst <= (eps2 * fabsf(dget(mm - 1))) * fabsf(dget(mm - 2)) + safmin) {
                            m2 = mm; break;
                        }
                    }
                }
                if (m2 > lend) eset(m2 - 2, 0.f);
                float p = dget(l - 1);
                if (m2 == l) {
                    dset(l - 1, p); l--;
                    if (l >= lend) continue;
                    break;
                }
                if (m2 == l - 1) {
                    float rt1, rt2, c2, s2;
                    f_slaev2(dget(l - 2), eget(l - 2), dget(l - 1), rt1, rt2, c2, s2);
                    zrot(l - 2, c2, s2);
                    dset(l - 2, rt1); dset(l - 1, rt2); eset(l - 2, 0.f);
                    l -= 2;
                    if (l >= lend) continue;
                    break;
                }
                if (jtot == nmaxit) break;
                jtot++;
                float g = __fdiv_rn(dget(l - 2) - p, 2.f * eget(l - 2));
                float r = f_slapy2(g, 1.f);
                g = dget(m2 - 1) - p + __fdiv_rn(eget(l - 2), g + copysignf(r, g));
                float sv = 1.f, cv = 1.f;
                p = 0.f;
                for (int i = m2; i <= l - 1; i++) {
                    float f = sv * eget(i - 1);
                    float b = cv * eget(i - 1);
                    f_slartg(g, f, cv, sv, r);
                    if (i != m2) eset(i - 2, r);
                    g = dget(i - 1) - p;
                    r = (dget(i) - g) * sv + 2.f * cv * b;
                    p = sv * r;
                    dset(i - 1, g + p);
                    g = cv * r - b;
                    wcset(i - 1, cv); wsset(i - 1, sv);
                }
                int mm = l - m2 + 1;                  // slasr 'R','V','F'
                for (int j = 1; j <= mm - 1; j++) {
                    float cc = wcget(m2 + j - 2), ssv = wsget(m2 + j - 2);
                    zrot(m2 + j - 2, cc, ssv);
                }
                dset(l - 1, dget(l - 1) - p);
                eset(l - 2, g);
            }
        }
    }

    // ---- selection sort ascending (LAPACK convention: min swaps) ----
    #pragma unroll
    for (int ii = 2; ii <= 3; ii++) {
        int i = ii - 1, k = i;
        float p = dget(i - 1);
        for (int j = ii; j <= 3; j++)
            if (dget(j - 1) < p) { k = j; p = dget(j - 1); }
        if (k != i) {
            dset(k - 1, dget(i - 1)); dset(i - 1, p);
            zswap(i - 1, k - 1);
        }
    }

    // ---- sormtr: Z = H1 * Z (H1 acts on rows 1,2) ----
    if (tau1 != 0.f) {
        float t;
        t = z10 + v3 * z20; z10 -= tau1 * t; z20 -= tau1 * v3 * t;
        t = z11 + v3 * z21; z11 -= tau1 * t; z21 -= tau1 * v3 * t;
        t = z12 + v3 * z22; z12 -= tau1 * t; z22 -= tau1 * v3 * t;
    }

    zvx = z00; zvy = z10; zvz = z20;   // smallest eigval
    xvx = z02; xvy = z12; xvz = z22;   // largest eigval
}

// ------------------------- kernel A1: covariance ----------------------------
// One warp per group: coalesced load, butterfly reductions (bit-identical FP
// order to R14's phase 1), all-lane result; lanes 0-5 write the 6 cov terms.

__global__ __launch_bounds__(256) void lrf_cov(
    const float* __restrict__ nb)
{
    const size_t g  = (size_t)(blockIdx.x * 8) + (threadIdx.x >> 5);
    const int lane  = threadIdx.x & 31;

    const float2* sp = (const float2*)(nb + g * 192);
    const float2 A = sp[lane * 3 + 0];
    const float2 B = sp[lane * 3 + 1];
    const float2 C = sp[lane * 3 + 2];
    const float p0x = A.x, p0y = A.y, p0z = B.x;
    const float p1x = B.y, p1y = C.x, p1z = C.y;

    // weights exactly as reference: w = (max_norm - norm) / (sum + 1e-6)
    const float n0 = __fsqrt_rn(p0x * p0x + p0y * p0y + p0z * p0z);
    const float n1 = __fsqrt_rn(p1x * p1x + p1y * p1y + p1z * p1z);
    float mx = fmaxf(n0, n1);
    #pragma unroll
    for (int dd = 16; dd; dd >>= 1)
        mx = fmaxf(mx, __shfl_xor_sync(0xffffffffu, mx, dd));
    const float w0 = mx - n0, w1 = mx - n1;
    float swt = w0 + w1;
    #pragma unroll
    for (int dd = 16; dd; dd >>= 1)
        swt += __shfl_xor_sync(0xffffffffu, swt, dd);
    const float denom = swt + 1e-6f;
    const float q0 = __fdiv_rn(w0, denom);
    const float q1 = __fdiv_rn(w1, denom);

    // covariance over scaled_pos = 100*pos, term = (w*sp_k)*sp_l
    const float s0x = 100.f * p0x, s0y = 100.f * p0y, s0z = 100.f * p0z;
    const float s1x = 100.f * p1x, s1y = 100.f * p1y, s1z = 100.f * p1z;
    float cxx = (q0 * s0x) * s0x + (q1 * s1x) * s1x;
    float cxy = (q0 * s0y) * s0x + (q1 * s1y) * s1x;   // C[1][0]
    float cxz = (q0 * s0z) * s0x + (q1 * s1z) * s1x;   // C[2][0]
    float cyy = (q0 * s0y) * s0y + (q1 * s1y) * s1y;
    float cyz = (q0 * s0z) * s0y + (q1 * s1z) * s1y;   // C[2][1]
    float czz = (q0 * s0z) * s0z + (q1 * s1z) * s1z;
    #pragma unroll
    for (int dd = 16; dd; dd >>= 1) {
        cxx += __shfl_xor_sync(0xffffffffu, cxx, dd);
        cxy += __shfl_xor_sync(0xffffffffu, cxy, dd);
        cxz += __shfl_xor_sync(0xffffffffu, cxz, dd);
        cyy += __shfl_xor_sync(0xffffffffu, cyy, dd);
        cyz += __shfl_xor_sync(0xffffffffu, cyz, dd);
        czz += __shfl_xor_sync(0xffffffffu, czz, dd);
    }

    // lanes 0..5 write the 6 terms (one STG each, contiguous 24B per group)
    float val = cxx;
    if (lane == 1) val = cxy;
    else if (lane == 2) val = cxz;
    else if (lane == 3) val = cyy;
    else if (lane == 4) val = cyz;
    else if (lane == 5) val = czz;
    if (lane < 6) g_cov[g * 6 + lane] = val;
}

// --------------------------- kernel A2: solve -------------------------------
// One solve per lane; warp w covers groups [32w, 32w+32). Compute-only.

__global__ __launch_bounds__(256, 4) void lrf_solve()
{
    const int warp_id = (blockIdx.x * 256 + threadIdx.x) >> 5;
    const int lane    = threadIdx.x & 31;
    const size_t g    = (size_t)warp_id * GPW + lane;

    const float* cp = g_cov + g * 6;
    const float c0 = cp[0], c1 = cp[1], c2 = cp[2];
    const float c3 = cp[3], c4 = cp[4], c5 = cp[5];

    float ezx, ezy, ezz, exx, exy, exz;
    eigh3_lapack(c0, c1, c2, c3, c4, c5, ezx, ezy, ezz, exx, exy, exz);

    float* v = g_vecs + g * 6;
    v[0] = ezx; v[1] = ezy; v[2] = ezz;
    v[3] = exx; v[4] = exy; v[5] = exz;
}

// ------------------------ kernel B: disambiguate+rotate ---------------------
// One warp per group; low registers, full occupancy, pure streaming.

__global__ __launch_bounds__(256) void lrf_rotate(
    const float* __restrict__ nb, float* __restrict__ out)
{
    const size_t g   = (size_t)(blockIdx.x * 8) + (threadIdx.x >> 5);
    const int lane   = threadIdx.x & 31;

    const float2* sp = (const float2*)(nb + g * 192);
    const float2 A = sp[lane * 3 + 0];
    const float2 B = sp[lane * 3 + 1];
    const float2 C = sp[lane * 3 + 2];
    const float p0x = A.x, p0y = A.y, p0z = B.x;
    const float p1x = B.y, p1y = C.x, p1z = C.y;

    const float* v = g_vecs + g * 6;
    float zx = v[0], zy = v[1], zz = v[2];
    float xx = v[3], xy = v[4], xz = v[5];

    // flip if #(pos . v > 0) < 32 ; tie keeps eigh's sign
    {
        float pj0 = zx * p0x + zy * p0y + zz * p0z;
        float pj1 = zx * p1x + zy * p1y + zz * p1z;
        int npos = __popc(__ballot_sync(0xffffffffu, pj0 > 0.f)) +
                   __popc(__ballot_sync(0xffffffffu, pj1 > 0.f));
        if (npos < 32) { zx = -zx; zy = -zy; zz = -zz; }
    }
    {
        float pj0 = xx * p0x + xy * p0y + xz * p0z;
        float pj1 = xx * p1x + xy * p1y + xz * p1z;
        int npos = __popc(__ballot_sync(0xffffffffu, pj0 > 0.f)) +
                   __popc(__ballot_sync(0xffffffffu, pj1 > 0.f));
        if (npos < 32) { xx = -xx; xy = -xy; xz = -xz; }
    }

    // y = z x x
    const float yx = zy * xz - zz * xy;
    const float yy = zz * xx - zx * xz;
    const float yz = zx * xy - zy * xx;

    // lrfs: rows = component, cols = (z, y, x)
    if (lane == 0) {
        float* L = out + ROT_ELEMS + g * 9;
        L[0] = zx; L[1] = yx; L[2] = xx;
        L[3] = zy; L[4] = yy; L[5] = xy;
        L[6] = zz; L[7] = yz; L[8] = xz;
    }

    // rot_neighbor = pos @ lrfs : per point (dot z, dot y, dot x)
    const float r0z = p0x * zx + p0y * zy + p0z * zz;
    const float r0y = p0x * yx + p0y * yy + p0z * yz;
    const float r0x = p0x * xx + p0y * xy + p0z * xz;
    const float r1z = p1x * zx + p1y * zy + p1z * zz;
    const float r1y = p1x * yx + p1y * yy + p1z * yz;
    const float r1x = p1x * xx + p1y * xy + p1z * xz;

    float2* dp = (float2*)(out + g * 192);
    dp[lane * 3 + 0] = make_float2(r0z, r0y);
    dp[lane * 3 + 1] = make_float2(r0x, r1z);
    dp[lane * 3 + 2] = make_float2(r1y, r1x);
}

extern "C" void kernel_launch(void* const* d_in, const int* in_sizes, int n_in,
                              void* d_out, int out_size) {
    const float* neighbor = (const float*)d_in[0];
    float* out = (float*)d_out;
    // A1: 1 warp/group -> 16384 blocks of 8 warps (full occupancy stream)
    lrf_cov<<<NG / 8, 256>>>(neighbor);
    // A2: one solve per lane -> 512 blocks (compute-only)
    lrf_solve<<<NG / (8 * GPW), 256>>>();
    // B : 1 warp/group -> 16384 blocks (full occupancy stream)
    lrf_rotate<<<NG / 8, 256>>>(neighbor, out);
}

// round 17
// speedup vs baseline: 1.0760x; 1.0760x over previous
#include <cuda_runtime.h>

// LRF_11330123727115
// Inputs : d_in[0] = neighbor (B=64, G=2048, S=64, C=3) float32 (center unused)
// Output : d_out = [ rot_neighbor (B,G,S,3) | lrfs (B,G,3,3) ] float32
//
// R17: three-kernel split. A1's covariance values are BIT-IDENTICAL to the
// passing R15 kernel (R16 failed because ~1-2 knife-edge groups flip sign on
// any ulp change of the covariance): 100x scaling and product order restored;
// the reduction does 3 shared butterfly levels (xor16/8/4, identical adds),
// a local per-lane term select, then xor2+xor1 — by commutativity of fp add
// this reproduces R15's stored values exactly with 20 SHFLs instead of 30.
//   A1 lrf_cov   (grid 16384, 1 warp/group): covariance -> g_cov.
//   A2 lrf_solve (grid 1024, block 128): LAPACK-faithful solve per lane.
//   B  lrf_rotate(grid 16384, 1 warp/group): disambiguate + rotate + store.
// Eigenvector signs match jnp.linalg.eigh (ssytd2+ssteqr+sormtr fp32
// emulation) — required for the n_pos==32 disambiguation ties (~9.9%/axis).

constexpr int NG = 64 * 2048;   // 131072 groups
constexpr long long ROT_ELEMS = (long long)NG * 64 * 3;
constexpr int GPW = 32;         // groups per warp in lrf_solve

__device__ float g_cov [NG * 6];   // per-group packed lower cov
__device__ float g_vecs[NG * 6];   // per-group z(3), x(3) eigenvectors

// ---------------- LAPACK helper emulations (fp32, IEEE ops) ----------------

__device__ __forceinline__ float f_slapy2(float x, float y) {
    float ax = fabsf(x), ay = fabsf(y);
    float w = fmaxf(ax, ay), z = fminf(ax, ay);
    if (z == 0.f) return w;
    float q = __fdiv_rn(z, w);
    return w * __fsqrt_rn(1.f + q * q);
}

// LAPACK >= 3.10 slartg: r = sign(f)*sqrt(f^2+g^2), c = |f|/|r| >= 0, s = g/r
__device__ __forceinline__ void f_slartg(float f, float g, float& c, float& s, float& r) {
    if (g == 0.f)      { c = 1.f; s = 0.f; r = f; }
    else if (f == 0.f) { c = 0.f; s = copysignf(1.f, g); r = fabsf(g); }
    else {
        float d = __fsqrt_rn(f * f + g * g);
        c = __fdiv_rn(fabsf(f), d);
        r = copysignf(d, f);
        s = __fdiv_rn(g, r);
    }
}

__device__ __forceinline__ void f_slaev2(float a, float b, float c,
                                         float& rt1, float& rt2,
                                         float& cs1, float& sn1) {
    float sm = a + c, df = a - c;
    float adf = fabsf(df), tb = b + b, ab = fabsf(tb);
    float acmx, acmn;
    if (fabsf(a) > fabsf(c)) { acmx = a; acmn = c; } else { acmx = c; acmn = a; }
    float rt;
    if (adf > ab)      { float q = __fdiv_rn(ab, adf); rt = adf * __fsqrt_rn(1.f + q * q); }
    else if (adf < ab) { float q = __fdiv_rn(adf, ab); rt = ab * __fsqrt_rn(1.f + q * q); }
    else               rt = ab * __fsqrt_rn(2.f);
    int sgn1;
    if (sm < 0.f) {
        rt1 = 0.5f * (sm - rt); sgn1 = -1;
        rt2 = __fdiv_rn(acmx, rt1) * acmn - __fdiv_rn(b, rt1) * b;
    } else if (sm > 0.f) {
        rt1 = 0.5f * (sm + rt); sgn1 = 1;
        rt2 = __fdiv_rn(acmx, rt1) * acmn - __fdiv_rn(b, rt1) * b;
    } else {
        rt1 = 0.5f * rt; rt2 = -0.5f * rt; sgn1 = 1;
    }
    int sgn2; float cs;
    if (df >= 0.f) { cs = df + rt; sgn2 = 1; }
    else           { cs = df - rt; sgn2 = -1; }
    float acs = fabsf(cs);
    if (acs > ab) {
        float ct = __fdiv_rn(-tb, cs);
        sn1 = __fdiv_rn(1.f, __fsqrt_rn(1.f + ct * ct));
        cs1 = ct * sn1;
    } else if (ab == 0.f) {
        cs1 = 1.f; sn1 = 0.f;
    } else {
        float tn = __fdiv_rn(-cs, tb);
        cs1 = __fdiv_rn(1.f, __fsqrt_rn(1.f + tn * tn));
        sn1 = tn * cs1;
    }
    if (sgn1 == sgn2) { float tn = cs1; cs1 = -sn1; sn1 = tn; }
}

// ssyevd(n=3, uplo='L') emulation: ssytd2 -> ssteqr('I') -> sort -> sormtr.
// Fully register-resident. FP op sequence identical to R5..R15.
__device__ void eigh3_lapack(float a11, float a21, float a31,
                             float a22, float a32, float a33,
                             float& zvx, float& zvy, float& zvz,
                             float& xvx, float& xvy, float& xvz) {
    // ---- ssytd2 lower: one reflector annihilating a31 ----
    float d0, d1, d2, e0, e1, tau1, v3;
    {
        float xnorm = fabsf(a31);
        if (xnorm == 0.f) { tau1 = 0.f; v3 = 0.f; e0 = a21; }
        else {
            float beta = -copysignf(f_slapy2(a21, xnorm), a21);
            tau1 = __fdiv_rn(beta - a21, beta);
            v3 = a31 * __fdiv_rn(1.f, a21 - beta);
            e0 = beta;
        }
        if (tau1 != 0.f) {
            float x1 = tau1 * (a22 + a32 * v3);   // x = tau*A22*v, v=[1,v3]
            float x2 = tau1 * (a32 + a33 * v3);
            float al = -0.5f * tau1 * (x1 + x2 * v3);
            float w1 = x1 + al;
            float w2 = x2 + al * v3;
            a22 = a22 - w1 - w1;                  // A -= v w^T + w v^T
            a32 = a32 - v3 * w1 - w2;
            a33 = a33 - v3 * w2 - v3 * w2;
        }
        d0 = a11; d1 = a22; d2 = a33; e1 = a32;
    }

    // Z kept as 9 registers, z<row><col>
    float z00 = 1.f, z01 = 0.f, z02 = 0.f;
    float z10 = 0.f, z11 = 1.f, z12 = 0.f;
    float z20 = 0.f, z21 = 0.f, z22 = 1.f;

    auto dget = [&](int i) -> float { return i == 0 ? d0 : (i == 1 ? d1 : d2); };
    auto dset = [&](int i, float v) { if (i == 0) d0 = v; else if (i == 1) d1 = v; else d2 = v; };
    auto eget = [&](int i) -> float { return i == 0 ? e0 : e1; };
    auto eset = [&](int i, float v) { if (i == 0) e0 = v; else e1 = v; };
    auto zrot = [&](int lo, float cc, float ss) {
        float t;
        if (lo == 0) {
            t = z01; z01 = cc * t - ss * z00; z00 = ss * t + cc * z00;
            t = z11; z11 = cc * t - ss * z10; z10 = ss * t + cc * z10;
            t = z21; z21 = cc * t - ss * z20; z20 = ss * t + cc * z20;
        } else {
            t = z02; z02 = cc * t - ss * z01; z01 = ss * t + cc * z01;
            t = z12; z12 = cc * t - ss * z11; z11 = ss * t + cc * z11;
            t = z22; z22 = cc * t - ss * z21; z21 = ss * t + cc * z21;
        }
    };
    auto zswap = [&](int a, int b) {   // swap columns a<b
        float t;
        if (a == 0 && b == 1) {
            t = z00; z00 = z01; z01 = t;
            t = z10; z10 = z11; z11 = t;
            t = z20; z20 = z21; z21 = t;
        } else if (a == 0 && b == 2) {
            t = z00; z00 = z02; z02 = t;
            t = z10; z10 = z12; z12 = t;
            t = z20; z20 = z22; z22 = t;
        } else {
            t = z01; z01 = z02; z02 = t;
            t = z11; z11 = z12; z12 = t;
            t = z21; z21 = z22; z22 = t;
        }
    };

    // ---- ssteqr('I', n=3) ----
    const float eps    = 5.9604645e-08f;   // slamch('E') for IEEE single
    const float eps2   = eps * eps;
    const float safmin = 1.1754944e-38f;
    const int   nmaxit = 90;               // 3 * 30
    int jtot = 0, l1 = 1;
    float wc0 = 0.f, wc1 = 0.f, ws0 = 0.f, ws1 = 0.f;
    auto wcget = [&](int i) -> float { return i == 0 ? wc0 : wc1; };
    auto wsget = [&](int i) -> float { return i == 0 ? ws0 : ws1; };
    auto wcset = [&](int i, float v) { if (i == 0) wc0 = v; else wc1 = v; };
    auto wsset = [&](int i, float v) { if (i == 0) ws0 = v; else ws1 = v; };

    for (;;) {                                       // label 10
        if (l1 > 3) break;
        if (l1 > 1) eset(l1 - 2, 0.f);
        int m = 3;
        if (l1 <= 2) {
            for (int mm = l1; mm <= 2; mm++) {
                float tst = fabsf(eget(mm - 1));
                if (tst == 0.f) { m = mm; break; }
                if (tst <= (__fsqrt_rn(fabsf(dget(mm - 1))) *
                            __fsqrt_rn(fabsf(dget(mm)))) * eps) {
                    eset(mm - 1, 0.f); m = mm; break;
                }
            }
        }
        int l = l1, lsv = l, lend = m, lendsv = lend;
        l1 = m + 1;
        if (lend == l) continue;
        float anorm = 0.f;
        for (int i = l; i <= lend; i++)     anorm = fmaxf(anorm, fabsf(dget(i - 1)));
        for (int i = l; i <= lend - 1; i++) anorm = fmaxf(anorm, fabsf(eget(i - 1)));
        if (anorm == 0.f) continue;
        if (fabsf(dget(lend - 1)) < fabsf(dget(l - 1))) { lend = lsv; l = lendsv; }

        if (lend > l) {
            // ================= QL iteration =================
            for (;;) {                                // label 40
                int m2 = lend;
                if (l != lend) {
                    for (int mm = l; mm <= lend - 1; mm++) {
                        float ev = eget(mm - 1);
                        float tst = ev * ev;
                        if (tst <= (eps2 * fabsf(dget(mm - 1))) * fabsf(dget(mm)) + safmin) {
                            m2 = mm; break;
                        }
                    }
                }
                if (m2 < lend) eset(m2 - 1, 0.f);
                float p = dget(l - 1);
                if (m2 == l) {                        // eigenvalue found
                    dset(l - 1, p); l++;
                    if (l <= lend) continue;
                    break;
                }
                if (m2 == l + 1) {                    // 2x2 deflation
                    float rt1, rt2, c2, s2;
                    f_slaev2(dget(l - 1), eget(l - 1), dget(l), rt1, rt2, c2, s2);
                    zrot(l - 1, c2, s2);
                    dset(l - 1, rt1); dset(l, rt2); eset(l - 1, 0.f);
                    l += 2;
                    if (l <= lend) continue;
                    break;
                }
                if (jtot == nmaxit) break;
                jtot++;
                float g = __fdiv_rn(dget(l) - p, 2.f * eget(l - 1));
                float r = f_slapy2(g, 1.f);
                g = dget(m2 - 1) - p + __fdiv_rn(eget(l - 1), g + copysignf(r, g));
                float sv = 1.f, cv = 1.f;
                p = 0.f;
                for (int i = m2 - 1; i >= l; i--) {
                    float f = sv * eget(i - 1);
                    float b = cv * eget(i - 1);
                    f_slartg(g, f, cv, sv, r);
                    if (i != m2 - 1) eset(i, r);
                    g = dget(i) - p;
                    r = (dget(i - 1) - g) * sv + 2.f * cv * b;
                    p = sv * r;
                    dset(i, g + p);
                    g = cv * r - b;
                    wcset(i - 1, cv); wsset(i - 1, -sv);
                }
                int mm = m2 - l + 1;                  // slasr 'R','V','B'
                for (int j = mm - 1; j >= 1; j--) {
                    float cc = wcget(l + j - 2), ssv = wsget(l + j - 2);
                    zrot(l + j - 2, cc, ssv);
                }
                dset(l - 1, dget(l - 1) - p);
                eset(l - 1, g);
            }
        } else {
            // ================= QR iteration =================
            for (;;) {                                // label 90
                int m2 = lend;
                if (l != lend) {
                    for (int mm = l; mm >= lend + 1; mm--) {
                        float ev = eget(mm - 2);
                        float tst = ev * ev;
                        if (tst <= (eps2 * fabsf(dget(mm - 1))) * fabsf(dget(mm - 2)) + safmin) {
                            m2 = mm; break;
                        }
                    }
                }
                if (m2 > lend) eset(m2 - 2, 0.f);
                float p = dget(l - 1);
                if (m2 == l) {
                    dset(l - 1, p); l--;
                    if (l >= lend) continue;
                    break;
                }
                if (m2 == l - 1) {
                    float rt1, rt2, c2, s2;
                    f_slaev2(dget(l - 2), eget(l - 2), dget(l - 1), rt1, rt2, c2, s2);
                    zrot(l - 2, c2, s2);
                    dset(l - 2, rt1); dset(l - 1, rt2); eset(l - 2, 0.f);
                    l -= 2;
                    if (l >= lend) continue;
                    break;
                }
                if (jtot == nmaxit) break;
                jtot++;
                float g = __fdiv_rn(dget(l - 2) - p, 2.f * eget(l - 2));
                float r = f_slapy2(g, 1.f);
                g = dget(m2 - 1) - p + __fdiv_rn(eget(l - 2), g + copysignf(r, g));
                float sv = 1.f, cv = 1.f;
                p = 0.f;
                for (int i = m2; i <= l - 1; i++) {
                    float f = sv * eget(i - 1);
                    float b = cv * eget(i - 1);
                    f_slartg(g, f, cv, sv, r);
                    if (i != m2) eset(i - 2, r);
                    g = dget(i - 1) - p;
                    r = (dget(i) - g) * sv + 2.f * cv * b;
                    p = sv * r;
                    dset(i - 1, g + p);
                    g = cv * r - b;
                    wcset(i - 1, cv); wsset(i - 1, sv);
                }
                int mm = l - m2 + 1;                  // slasr 'R','V','F'
                for (int j = 1; j <= mm - 1; j++) {
                    float cc = wcget(m2 + j - 2), ssv = wsget(m2 + j - 2);
                    zrot(m2 + j - 2, cc, ssv);
                }
                dset(l - 1, dget(l - 1) - p);
                eset(l - 2, g);
            }
        }
    }

    // ---- selection sort ascending (LAPACK convention: min swaps) ----
    #pragma unroll
    for (int ii = 2; ii <= 3; ii++) {
        int i = ii - 1, k = i;
        float p = dget(i - 1);
        for (int j = ii; j <= 3; j++)
            if (dget(j - 1) < p) { k = j; p = dget(j - 1); }
        if (k != i) {
            dset(k - 1, dget(i - 1)); dset(i - 1, p);
            zswap(i - 1, k - 1);
        }
    }

    // ---- sormtr: Z = H1 * Z (H1 acts on rows 1,2) ----
    if (tau1 != 0.f) {
        float t;
        t = z10 + v3 * z20; z10 -= tau1 * t; z20 -= tau1 * v3 * t;
        t = z11 + v3 * z21; z11 -= tau1 * t; z21 -= tau1 * v3 * t;
        t = z12 + v3 * z22; z12 -= tau1 * t; z22 -= tau1 * v3 * t;
    }

    zvx = z00; zvy = z10; zvz = z20;   // smallest eigval
    xvx = z02; xvy = z12; xvz = z22;   // largest eigval
}

// ------------------------- kernel A1: covariance ----------------------------
// One warp per group. R15 arithmetic restored verbatim (100x scaling,
// (q*s_k)*s_l products, same butterfly adds). The reduction runs 3 shared
// butterfly levels (xor16/8/4), then lane 4q+r locally selects term q's
// residue-r partial, then xor2+xor1 finish: by fp-add commutativity the
// stored lane-4q value equals R15's result BIT-FOR-BIT, using 20 SHFLs.

__global__ __launch_bounds__(256) void lrf_cov(
    const float* __restrict__ nb)
{
    const size_t g  = (size_t)(blockIdx.x * 8) + (threadIdx.x >> 5);
    const int lane  = threadIdx.x & 31;

    const float2* sp = (const float2*)(nb + g * 192);
    const float2 A = sp[lane * 3 + 0];
    const float2 B = sp[lane * 3 + 1];
    const float2 C = sp[lane * 3 + 2];
    const float p0x = A.x, p0y = A.y, p0z = B.x;
    const float p1x = B.y, p1y = C.x, p1z = C.y;

    // weights exactly as reference: w = (max_norm - norm) / (sum + 1e-6)
    const float n0 = __fsqrt_rn(p0x * p0x + p0y * p0y + p0z * p0z);
    const float n1 = __fsqrt_rn(p1x * p1x + p1y * p1y + p1z * p1z);
    float mx = fmaxf(n0, n1);
    #pragma unroll
    for (int dd = 16; dd; dd >>= 1)
        mx = fmaxf(mx, __shfl_xor_sync(0xffffffffu, mx, dd));
    const float w0 = mx - n0, w1 = mx - n1;
    float swt = w0 + w1;
    #pragma unroll
    for (int dd = 16; dd; dd >>= 1)
        swt += __shfl_xor_sync(0xffffffffu, swt, dd);
    const float denom = swt + 1e-6f;
    const float q0 = __fdiv_rn(w0, denom);
    const float q1 = __fdiv_rn(w1, denom);

    // covariance over scaled_pos = 100*pos, term = (w*sp_k)*sp_l (R15 exact)
    const float s0x = 100.f * p0x, s0y = 100.f * p0y, s0z = 100.f * p0z;
    const float s1x = 100.f * p1x, s1y = 100.f * p1y, s1z = 100.f * p1z;
    float cxx = (q0 * s0x) * s0x + (q1 * s1x) * s1x;
    float cxy = (q0 * s0y) * s0x + (q1 * s1y) * s1x;   // C[1][0]
    float cxz = (q0 * s0z) * s0x + (q1 * s1z) * s1x;   // C[2][0]
    float cyy = (q0 * s0y) * s0y + (q1 * s1y) * s1y;
    float cyz = (q0 * s0z) * s0y + (q1 * s1z) * s1y;   // C[2][1]
    float czz = (q0 * s0z) * s0z + (q1 * s1z) * s1z;

    // 3 shared butterfly levels: lane i then holds residue-(i&3) partial
    #pragma unroll
    for (int dd = 16; dd >= 4; dd >>= 1) {
        cxx += __shfl_xor_sync(0xffffffffu, cxx, dd);
        cxy += __shfl_xor_sync(0xffffffffu, cxy, dd);
        cxz += __shfl_xor_sync(0xffffffffu, cxz, dd);
        cyy += __shfl_xor_sync(0xffffffffu, cyy, dd);
        cyz += __shfl_xor_sync(0xffffffffu, cyz, dd);
        czz += __shfl_xor_sync(0xffffffffu, czz, dd);
    }
    // local select: lane 4q+r takes term q's residue-r partial (no shfl)
    const int qsel = lane >> 2;            // 0..7 (6,7 unused)
    float t = (qsel == 0) ? cxx :
              (qsel == 1) ? cxy :
              (qsel == 2) ? cxz :
              (qsel == 3) ? cyy :
              (qsel == 4) ? cyz : czz;
    // finish xor2 THEN xor1 (matches the full butterfly's association:
    // lane 4q ends with (c0+c2)+(c1+c3) — bit-identical to R15)
    t += __shfl_xor_sync(0xffffffffu, t, 2);
    t += __shfl_xor_sync(0xffffffffu, t, 1);
    if (lane < 24 && (lane & 3) == 0)
        g_cov[g * 6 + qsel] = t;
}

// --------------------------- kernel A2: solve -------------------------------
// One solve per lane; warp w covers groups [32w, 32w+32). Compute-only.
// Block 128 for finer SM load balance (1024 blocks over 148 SMs).

__global__ __launch_bounds__(128, 8) void lrf_solve()
{
    const int warp_id = (blockIdx.x * 128 + threadIdx.x) >> 5;
    const int lane    = threadIdx.x & 31;
    const size_t g    = (size_t)warp_id * GPW + lane;

    const float* cp = g_cov + g * 6;
    const float c0 = cp[0], c1 = cp[1], c2 = cp[2];
    const float c3 = cp[3], c4 = cp[4], c5 = cp[5];

    float ezx, ezy, ezz, exx, exy, exz;
    eigh3_lapack(c0, c1, c2, c3, c4, c5, ezx, ezy, ezz, exx, exy, exz);

    float* v = g_vecs + g * 6;
    v[0] = ezx; v[1] = ezy; v[2] = ezz;
    v[3] = exx; v[4] = exy; v[5] = exz;
}

// ------------------------ kernel B: disambiguate+rotate ---------------------
// One warp per group; low registers, full occupancy, pure streaming.
// lrfs stored by lanes 0..8 (one coalesced STG) with values identical to R15.

__global__ __launch_bounds__(256) void lrf_rotate(
    const float* __restrict__ nb, float* __restrict__ out)
{
    const size_t g   = (size_t)(blockIdx.x * 8) + (threadIdx.x >> 5);
    const int lane   = threadIdx.x & 31;

    const float2* sp = (const float2*)(nb + g * 192);
    const float2 A = sp[lane * 3 + 0];
    const float2 B = sp[lane * 3 + 1];
    const float2 C = sp[lane * 3 + 2];
    const float p0x = A.x, p0y = A.y, p0z = B.x;
    const float p1x = B.y, p1y = C.x, p1z = C.y;

    const float* v = g_vecs + g * 6;
    float zx = v[0], zy = v[1], zz = v[2];
    float xx = v[3], xy = v[4], xz = v[5];

    // flip if #(pos . v > 0) < 32 ; tie keeps eigh's sign
    {
        float pj0 = zx * p0x + zy * p0y + zz * p0z;
        float pj1 = zx * p1x + zy * p1y + zz * p1z;
        int npos = __popc(__ballot_sync(0xffffffffu, pj0 > 0.f)) +
                   __popc(__ballot_sync(0xffffffffu, pj1 > 0.f));
        if (npos < 32) { zx = -zx; zy = -zy; zz = -zz; }
    }
    {
        float pj0 = xx * p0x + xy * p0y + xz * p0z;
        float pj1 = xx * p1x + xy * p1y + xz * p1z;
        int npos = __popc(__ballot_sync(0xffffffffu, pj0 > 0.f)) +
                   __popc(__ballot_sync(0xffffffffu, pj1 > 0.f));
        if (npos < 32) { xx = -xx; xy = -xy; xz = -xz; }
    }

    // y = z x x
    const float yx = zy * xz - zz * xy;
    const float yy = zz * xx - zx * xz;
    const float yz = zx * xy - zy * xx;

    // lrfs: rows = component, cols = (z, y, x); lanes 0..8 write coalesced
    {
        float lv = zx;
        if      (lane == 1) lv = yx;
        else if (lane == 2) lv = xx;
        else if (lane == 3) lv = zy;
        else if (lane == 4) lv = yy;
        else if (lane == 5) lv = xy;
        else if (lane == 6) lv = zz;
        else if (lane == 7) lv = yz;
        else if (lane == 8) lv = xz;
        if (lane < 9)
            __stcs(out + ROT_ELEMS + g * 9 + lane, lv);
    }

    // rot_neighbor = pos @ lrfs : per point (dot z, dot y, dot x)
    const float r0z = p0x * zx + p0y * zy + p0z * zz;
    const float r0y = p0x * yx + p0y * yy + p0z * yz;
    const float r0x = p0x * xx + p0y * xy + p0z * xz;
    const float r1z = p1x * zx + p1y * zy + p1z * zz;
    const float r1y = p1x * yx + p1y * yy + p1z * yz;
    const float r1x = p1x * xx + p1y * xy + p1z * xz;

    float2* dp = (float2*)(out + g * 192);
    __stcs(dp + lane * 3 + 0, make_float2(r0z, r0y));
    __stcs(dp + lane * 3 + 1, make_float2(r0x, r1z));
    __stcs(dp + lane * 3 + 2, make_float2(r1y, r1x));
}

extern "C" void kernel_launch(void* const* d_in, const int* in_sizes, int n_in,
                              void* d_out, int out_size) {
    const float* neighbor = (const float*)d_in[0];
    float* out = (float*)d_out;
    // A1: 1 warp/group -> 16384 blocks of 8 warps (full occupancy stream)
    lrf_cov<<<NG / 8, 256>>>(neighbor);
    // A2: one solve per lane -> 1024 blocks of 128 threads (compute-only)
    lrf_solve<<<NG / (4 * GPW), 128>>>();
    // B : 1 warp/group -> 16384 blocks (full occupancy stream)
    lrf_rotate<<<NG / 8, 256>>>(neighbor, out);
}